// round 11
// baseline (speedup 1.0000x reference)
#include <cuda_runtime.h>

// ---------------------------------------------------------------------------
// Fused spatio-temporal GCN, one 256-thread CTA per (b,t), 1 CTA/SM.
// Stage-3 tile: 12 rows x 8 cols per thread (0.83 smem-lane-bytes per MAC),
// 2-way m-split with halves in SEPARATE warps; cross-half reduce via smem.
// All operands in smem, cp.async double-pumped; packed fma.rn.f32x2 math.
// ---------------------------------------------------------------------------

#define FINq 3
#define NV   170
#define CPAD 172          // cheb col pad (zeros at 170,171)
#define TMP  68           // Tm row pad (16B rows)
#define TTq  288
#define HH   64
#define OO   64
#define KK   3
#define NT   256
#define R3   12           // stage3 rows/thread (15 groups x 12 = 180)
#define NR3  180
#define R2   6            // stage2 rows/thread (29 groups x 6 = 174)

typedef unsigned long long ull;

__device__ __forceinline__ ull f2fma(ull a, ull b, ull c) {
    ull d;
    asm("fma.rn.f32x2 %0, %1, %2, %3;" : "=l"(d) : "l"(a), "l"(b), "l"(c));
    return d;
}
__device__ __forceinline__ ull f2add(ull a, ull b) {
    ull d;
    asm("add.rn.f32x2 %0, %1, %2;" : "=l"(d) : "l"(a), "l"(b));
    return d;
}
__device__ __forceinline__ ull f2dup(float a) {
    ull d;
    asm("mov.b64 %0, {%1, %1};" : "=l"(d) : "f"(a));
    return d;
}
__device__ __forceinline__ float2 f2un(ull p) {
    float2 r;
    asm("mov.b64 {%0, %1}, %2;" : "=f"(r.x), "=f"(r.y) : "l"(p));
    return r;
}
__device__ __forceinline__ unsigned s2u(const void* p) {
    unsigned a;
    asm("{ .reg .u64 t; cvta.to.shared.u64 t, %1; cvt.u32.u64 %0, t; }"
        : "=r"(a) : "l"(p));
    return a;
}
#define CPA16(d, s) asm volatile("cp.async.cg.shared.global [%0], [%1], 16;" \
                                 :: "r"(d), "l"(s) : "memory")
#define CPCOMMIT()  asm volatile("cp.async.commit_group;" ::: "memory")
#define CPWAIT(n)   asm volatile("cp.async.wait_group %0;" :: "n"(n) : "memory")

// transposed cheb [k][n][m], m zero-padded to 172
__device__ __align__(16) float g_chebT[KK * NV * CPAD];

__global__ void prep_chebT(const float* __restrict__ cheb) {
    int idx = blockIdx.x * 256 + threadIdx.x;
    if (idx >= KK * NV * CPAD) return;
    int j  = idx % CPAD;
    int kn = idx / CPAD;
    g_chebT[idx] = (j < NV) ? cheb[kn * NV + j] : 0.0f;
}

// shared memory layout (float offsets)
#define WC_OFF   0                        // conv_w 576
#define WCB_OFF  576                      // conv_b 64
#define WRES_OFF 640                      // res_w 192
#define WRB_OFF  832                      // res_b 64
#define XRES_OFF 896                      // residual x taps 3*170=510 (pad 512)
#define CHS_OFF  1408                     // cheb slice 170*172 = 29240
#define XS_OFF   1408                     // x slice 1530 (overlaps chs)
#define TM_OFF   (CHS_OFF + NV * CPAD)    // 30648; Tm[m][68] 170*68 = 11560
#define V_OFF    (TM_OFF + NV * TMP)      // 42208; V[172][64] = 11008
#define THS_OFF  (V_OFF + CPAD * OO)      // 53216; thetaS 4096
#define SMEM_FLOATS (THS_OFF + HH * OO)   // 57312
#define SMEM_BYTES  (SMEM_FLOATS * 4)     // 229248 B (<= 232448)

#define CHEB_CHUNKS  ((NV * CPAD) / 4)    // 7310 x 16B
#define THETA_CHUNKS ((HH * OO) / 4)      // 1024 x 16B

__global__ void __launch_bounds__(NT, 1)
stgcn_fused_kernel(const float* __restrict__ x,
                   const float* __restrict__ theta,
                   const float* __restrict__ conv_w,
                   const float* __restrict__ conv_b,
                   const float* __restrict__ res_w,
                   const float* __restrict__ res_b,
                   float* __restrict__ out)
{
    extern __shared__ float sm[];
    float* wc   = sm + WC_OFF;
    float* wcb  = sm + WCB_OFF;
    float* wres = sm + WRES_OFF;
    float* wrb  = sm + WRB_OFF;
    float* xres = sm + XRES_OFF;
    float* xs   = sm + XS_OFF;
    float* chs  = sm + CHS_OFF;
    float* Tm   = sm + TM_OFF;
    float* Vv   = sm + V_OFF;
    float* ths  = sm + THS_OFF;
    const unsigned ths_u = s2u(ths);
    const unsigned chs_u = s2u(chs);

    const int t   = blockIdx.x;
    const int b   = blockIdx.y;
    const int tid = threadIdx.x;

    // ---- prefetch theta[0] ----
    for (int i = tid; i < THETA_CHUNKS; i += NT)
        CPA16(ths_u + i * 16, theta + (size_t)i * 4);
    CPCOMMIT();

    // ---------------- stage 0: xs + small weights ----------------
    for (int i = tid; i < FINq * 3 * NV; i += NT) {
        int f = i / (3 * NV);
        int r = i - f * (3 * NV);
        int s = r / NV;
        int m = r - s * NV;
        int tt = t + s - 1;
        float v = 0.0f;
        if (tt >= 0 && tt < TTq)
            v = x[((size_t)(b * FINq + f) * NV + m) * TTq + tt];
        xs[i] = v;                       // (f*3+s)*NV + m
    }
    for (int i = tid; i < HH * FINq * 3; i += NT) wc[i] = conv_w[i];
    if (tid < OO * FINq)              wres[tid]      = res_w[tid];
    else if (tid >= 192 && tid < 256) wcb[tid - 192] = conv_b[tid - 192];
    if (tid < OO)                     wrb[tid]       = res_b[tid];
    __syncthreads();

    // ---------------- stage 1: temporal conv + ReLU -> Tm[m][c] ----------------
    for (int idx = tid; idx < NV * HH; idx += NT) {
        int m = idx >> 6;
        int c = idx & 63;
        float v = wcb[c];
        #pragma unroll
        for (int f = 0; f < FINq; ++f)
            #pragma unroll
            for (int s = 0; s < 3; ++s)
                v = fmaf(xs[(f * 3 + s) * NV + m], wc[(c * FINq + f) * 3 + s], v);
        Tm[m * TMP + c] = fmaxf(v, 0.0f);
    }
    // save residual x center taps before xs region is recycled for cheb
    for (int i = tid; i < FINq * NV; i += NT) {
        int f = i / NV;
        int n = i - f * NV;
        xres[i] = xs[(f * 3 + 1) * NV + n];
    }
    __syncthreads();     // all xs reads + Tm writes done

    // ---- prefetch cheb[0] (overwrites xs region) ----
    for (int i = tid; i < CHEB_CHUNKS; i += NT)
        CPA16(chs_u + i * 16, g_chebT + (size_t)i * 4);
    CPCOMMIT();
    CPWAIT(1);           // theta[0] landed
    __syncthreads();

    // ---- thread mappings ----
    // stage 2: 6 rows x 8 cols, 29 groups
    const int o8s2 = (tid & 7) * 8;
    const int rg2  = tid >> 3;           // 0..31
    const int m20  = rg2 * R2;
    const bool act2 = (m20 < NV);        // rg2 <= 28

    // stage 3: 12 rows x 8 cols, m-split in 2 HALVES mapped to separate warps
    const int half = tid >> 7;           // warps 0-3: half 0, warps 4-7: half 1
    const int htid = tid & 127;
    const int o8   = (htid & 7) * 8;
    const int rg3  = htid >> 3;          // 0..15
    const int n0   = rg3 * R3;
    const bool act3 = (rg3 < 15);        // 120 threads per half
    const int mlo  = half ? 88 : 0;
    const int mhi  = half ? CPAD : 88;   // 22 / 21 quads

    int croff[R3];
    #pragma unroll
    for (int i = 0; i < R3; ++i) {
        int n = n0 + i;
        croff[i] = ((n < NV) ? n : (NV - 1)) * CPAD;
    }

    ull acc[R3][4];
    #pragma unroll
    for (int i = 0; i < R3; ++i)
        #pragma unroll
        for (int p = 0; p < 4; ++p) acc[i][p] = 0ull;

    for (int k = 0; k < KK; ++k) {
        // ------------- stage 2: V = Tm @ thetaS (6x8 tiles) -------------
        if (act2) {
            int mr[R2];
            #pragma unroll
            for (int i = 0; i < R2; ++i)
                mr[i] = (m20 + i < NV) ? (m20 + i) : (NV - 1);
            ull a2[R2][4];
            #pragma unroll
            for (int i = 0; i < R2; ++i)
                #pragma unroll
                for (int p = 0; p < 4; ++p) a2[i][p] = 0ull;

            for (int c = 0; c < HH; c += 4) {
                ulonglong2 th0a = *(const ulonglong2*)(ths + (c + 0) * OO + o8s2);
                ulonglong2 th0b = *(const ulonglong2*)(ths + (c + 0) * OO + o8s2 + 4);
                ulonglong2 th1a = *(const ulonglong2*)(ths + (c + 1) * OO + o8s2);
                ulonglong2 th1b = *(const ulonglong2*)(ths + (c + 1) * OO + o8s2 + 4);
                ulonglong2 th2a = *(const ulonglong2*)(ths + (c + 2) * OO + o8s2);
                ulonglong2 th2b = *(const ulonglong2*)(ths + (c + 2) * OO + o8s2 + 4);
                ulonglong2 th3a = *(const ulonglong2*)(ths + (c + 3) * OO + o8s2);
                ulonglong2 th3b = *(const ulonglong2*)(ths + (c + 3) * OO + o8s2 + 4);
                #pragma unroll
                for (int i = 0; i < R2; ++i) {
                    ulonglong2 tm4 = *(const ulonglong2*)(Tm + mr[i] * TMP + c);
                    float2 t01 = f2un(tm4.x);
                    float2 t23 = f2un(tm4.y);
                    ull d0 = f2dup(t01.x), d1 = f2dup(t01.y);
                    ull d2 = f2dup(t23.x), d3 = f2dup(t23.y);
                    a2[i][0] = f2fma(d0, th0a.x, a2[i][0]);
                    a2[i][1] = f2fma(d0, th0a.y, a2[i][1]);
                    a2[i][2] = f2fma(d0, th0b.x, a2[i][2]);
                    a2[i][3] = f2fma(d0, th0b.y, a2[i][3]);
                    a2[i][0] = f2fma(d1, th1a.x, a2[i][0]);
                    a2[i][1] = f2fma(d1, th1a.y, a2[i][1]);
                    a2[i][2] = f2fma(d1, th1b.x, a2[i][2]);
                    a2[i][3] = f2fma(d1, th1b.y, a2[i][3]);
                    a2[i][0] = f2fma(d2, th2a.x, a2[i][0]);
                    a2[i][1] = f2fma(d2, th2a.y, a2[i][1]);
                    a2[i][2] = f2fma(d2, th2b.x, a2[i][2]);
                    a2[i][3] = f2fma(d2, th2b.y, a2[i][3]);
                    a2[i][0] = f2fma(d3, th3a.x, a2[i][0]);
                    a2[i][1] = f2fma(d3, th3a.y, a2[i][1]);
                    a2[i][2] = f2fma(d3, th3b.x, a2[i][2]);
                    a2[i][3] = f2fma(d3, th3b.y, a2[i][3]);
                }
            }
            #pragma unroll
            for (int i = 0; i < R2; ++i) {
                int m = m20 + i;
                if (m < CPAD) {          // rows 170,171 hold junk x 0-cheb = ok
                    ulonglong2* dst = (ulonglong2*)(Vv + (size_t)m * OO + o8s2);
                    dst[0] = make_ulonglong2(a2[i][0], a2[i][1]);
                    dst[1] = make_ulonglong2(a2[i][2], a2[i][3]);
                }
            }
        }
        CPWAIT(0);          // chs[k] landed
        __syncthreads();    // V + chs visible

        if (k < KK - 1) {   // theta[k+1] prefetch rides under stage 3
            const float* tsrc = theta + (size_t)(k + 1) * HH * OO;
            for (int i = tid; i < THETA_CHUNKS; i += NT)
                CPA16(ths_u + i * 16, tsrc + (size_t)i * 4);
            CPCOMMIT();
        }

        // ------------- stage 3: acc += chs[n][m] * V[m][o8..+8), half m-range ----
        if (act3) {
            #pragma unroll 1
            for (int m = mlo; m < mhi; m += 4) {
                float4 cb[R3];
                #pragma unroll
                for (int i = 0; i < R3; ++i)
                    cb[i] = *(const float4*)(chs + croff[i] + m);
                const float* vp = Vv + (size_t)m * OO + o8;
                #pragma unroll
                for (int r = 0; r < 4; ++r) {
                    ulonglong2 va = *(const ulonglong2*)(vp + r * OO);
                    ulonglong2 vb = *(const ulonglong2*)(vp + r * OO + 4);
                    #pragma unroll
                    for (int i = 0; i < R3; ++i) {
                        float cs = (r == 0) ? cb[i].x : (r == 1) ? cb[i].y
                                 : (r == 2) ? cb[i].z : cb[i].w;
                        ull d = f2dup(cs);
                        acc[i][0] = f2fma(d, va.x, acc[i][0]);
                        acc[i][1] = f2fma(d, va.y, acc[i][1]);
                        acc[i][2] = f2fma(d, vb.x, acc[i][2]);
                        acc[i][3] = f2fma(d, vb.y, acc[i][3]);
                    }
                }
            }
        }
        __syncthreads();    // chs readers done before overwrite

        if (k < KK - 1) {
            const float* csrc = g_chebT + (size_t)(k + 1) * NV * CPAD;
            for (int i = tid; i < CHEB_CHUNKS; i += NT)
                CPA16(chs_u + i * 16, csrc + (size_t)i * 4);
            CPCOMMIT();
            CPWAIT(1);      // theta[k+1] ready (cheb[k+1] in flight)
            __syncthreads();
        }
    }

    // ---------------- cross-half reduce via chs region (now free) ----------------
    if (act3 && half == 1) {
        #pragma unroll
        for (int i = 0; i < R3; ++i) {
            ulonglong2* dst = (ulonglong2*)(chs + (size_t)(n0 + i) * OO + o8);
            dst[0] = make_ulonglong2(acc[i][0], acc[i][1]);
            dst[1] = make_ulonglong2(acc[i][2], acc[i][3]);
        }
    }
    __syncthreads();

    // ---------------- epilogue (half 0): add partner, relu + residual ----------------
    if (act3 && half == 0) {
        #pragma unroll
        for (int i = 0; i < R3; ++i) {
            int n = n0 + i;
            if (n >= NV) break;
            const ulonglong2* src = (const ulonglong2*)(chs + (size_t)n * OO + o8);
            ulonglong2 p0 = src[0], p1 = src[1];
            acc[i][0] = f2add(acc[i][0], p0.x);
            acc[i][1] = f2add(acc[i][1], p0.y);
            acc[i][2] = f2add(acc[i][2], p1.x);
            acc[i][3] = f2add(acc[i][3], p1.y);
            float x0 = xres[n];
            float x1 = xres[NV + n];
            float x2 = xres[2 * NV + n];
            #pragma unroll
            for (int p = 0; p < 4; ++p) {
                float2 gv = f2un(acc[i][p]);
                int o0 = o8 + 2 * p;
                float r0 = wrb[o0] + x0 * wres[o0 * 3 + 0]
                                   + x1 * wres[o0 * 3 + 1]
                                   + x2 * wres[o0 * 3 + 2];
                float r1 = wrb[o0 + 1] + x0 * wres[(o0 + 1) * 3 + 0]
                                       + x1 * wres[(o0 + 1) * 3 + 1]
                                       + x2 * wres[(o0 + 1) * 3 + 2];
                out[((size_t)(b * OO + o0)     * NV + n) * TTq + t] = fmaxf(gv.x, 0.0f) + r0;
                out[((size_t)(b * OO + o0 + 1) * NV + n) * TTq + t] = fmaxf(gv.y, 0.0f) + r1;
            }
        }
    }
}

extern "C" void kernel_launch(void* const* d_in, const int* in_sizes, int n_in,
                              void* d_out, int out_size)
{
    (void)in_sizes; (void)n_in; (void)out_size;
    const float* x      = (const float*)d_in[0];
    // d_in[1] = adj (unused by forward)
    const float* cheb   = (const float*)d_in[2];
    const float* conv_w = (const float*)d_in[3];
    const float* conv_b = (const float*)d_in[4];
    const float* theta  = (const float*)d_in[5];
    const float* res_w  = (const float*)d_in[6];
    const float* res_b  = (const float*)d_in[7];
    float* out = (float*)d_out;

    prep_chebT<<<(KK * NV * CPAD + 255) / 256, 256>>>(cheb);

    cudaFuncSetAttribute(stgcn_fused_kernel,
                         cudaFuncAttributeMaxDynamicSharedMemorySize, SMEM_BYTES);

    dim3 grid(TTq, 16);   // 4608 CTAs, one per (b, t)
    stgcn_fused_kernel<<<grid, NT, SMEM_BYTES>>>(
        x, theta, conv_w, conv_b, res_w, res_b, out);
}

// round 13
// speedup vs baseline: 1.2076x; 1.2076x over previous
#include <cuda_runtime.h>

// ---------------------------------------------------------------------------
// Fused spatio-temporal GCN, one 256-thread CTA per (b,t), 1 CTA/SM.
// Exact identity shortcut: cheb[0] = I, so the k=0 spatial GEMM is replaced by
// acc := V0 (register init from smem). Stage 3 runs only k = 1,2.
// Stage-3 tile: 12 rows x 8 cols per thread, 2-way m-split in separate warps,
// cross-half reduce via smem. All operands smem-resident, cp.async prefetched,
// packed fma.rn.f32x2 math throughout.
// ---------------------------------------------------------------------------

#define FINq 3
#define NV   170
#define CPAD 172          // cheb col pad (zeros at 170,171)
#define TMP  68           // Tm row pad (16B rows)
#define TTq  288
#define HH   64
#define OO   64
#define KK   3
#define NT   256
#define R3   12           // stage3 rows/thread (15 groups x 12 = 180)
#define R2   6            // stage2 rows/thread (29 groups x 6 = 174)

typedef unsigned long long ull;

__device__ __forceinline__ ull f2fma(ull a, ull b, ull c) {
    ull d;
    asm("fma.rn.f32x2 %0, %1, %2, %3;" : "=l"(d) : "l"(a), "l"(b), "l"(c));
    return d;
}
__device__ __forceinline__ ull f2add(ull a, ull b) {
    ull d;
    asm("add.rn.f32x2 %0, %1, %2;" : "=l"(d) : "l"(a), "l"(b));
    return d;
}
__device__ __forceinline__ ull f2dup(float a) {
    ull d;
    asm("mov.b64 %0, {%1, %1};" : "=l"(d) : "f"(a));
    return d;
}
__device__ __forceinline__ float2 f2un(ull p) {
    float2 r;
    asm("mov.b64 {%0, %1}, %2;" : "=f"(r.x), "=f"(r.y) : "l"(p));
    return r;
}
__device__ __forceinline__ unsigned s2u(const void* p) {
    unsigned a;
    asm("{ .reg .u64 t; cvta.to.shared.u64 t, %1; cvt.u32.u64 %0, t; }"
        : "=r"(a) : "l"(p));
    return a;
}
#define CPA16(d, s) asm volatile("cp.async.cg.shared.global [%0], [%1], 16;" \
                                 :: "r"(d), "l"(s) : "memory")
#define CPCOMMIT()  asm volatile("cp.async.commit_group;" ::: "memory")
#define CPWAIT(n)   asm volatile("cp.async.wait_group %0;" :: "n"(n) : "memory")

// transposed cheb for k = 1,2 only (k=0 is the identity): [k-1][n][m pad 172]
__device__ __align__(16) float g_chebT[2 * NV * CPAD];

__global__ void prep_chebT(const float* __restrict__ cheb) {
    int idx = blockIdx.x * 256 + threadIdx.x;
    if (idx >= 2 * NV * CPAD) return;
    int j  = idx % CPAD;
    int kn = idx / CPAD;          // 0 .. 2*NV-1
    int n  = kn % NV;
    int k  = kn / NV + 1;         // 1 or 2
    g_chebT[idx] = (j < NV) ? cheb[((size_t)k * NV + n) * NV + j] : 0.0f;
}

// shared memory layout (float offsets)
#define WC_OFF   0                        // conv_w 576
#define WCB_OFF  576                      // conv_b 64
#define WRES_OFF 640                      // res_w 192
#define WRB_OFF  832                      // res_b 64
#define XRES_OFF 896                      // residual x taps 3*170=510 (pad 512)
#define CHS_OFF  1408                     // cheb slice 170*172 = 29240
#define XS_OFF   1408                     // x slice 1530 (overlaps chs)
#define TM_OFF   (CHS_OFF + NV * CPAD)    // 30648; Tm[m][68] = 11560
#define V_OFF    (TM_OFF + NV * TMP)      // 42208; V[172][64] = 11008
#define THS_OFF  (V_OFF + CPAD * OO)      // 53216; thetaS 4096
#define SMEM_FLOATS (THS_OFF + HH * OO)   // 57312
#define SMEM_BYTES  (SMEM_FLOATS * 4)     // 229248 B (<= 232448)

#define CHEB_CHUNKS  ((NV * CPAD) / 4)    // 7310 x 16B
#define THETA_CHUNKS ((HH * OO) / 4)      // 1024 x 16B

// ---- stage 2: V = Tm @ theta_k, 6x8 fp32 register tiles ----
__device__ __forceinline__ void stage2_run(const float* __restrict__ thk,
                                           const float* __restrict__ Tm,
                                           float* __restrict__ Vv,
                                           int o8s2, int m20, bool act2)
{
    if (!act2) return;
    int mr[R2];
    #pragma unroll
    for (int i = 0; i < R2; ++i) mr[i] = (m20 + i < NV) ? (m20 + i) : (NV - 1);
    ull a2[R2][4];
    #pragma unroll
    for (int i = 0; i < R2; ++i)
        #pragma unroll
        for (int p = 0; p < 4; ++p) a2[i][p] = 0ull;

    for (int c = 0; c < HH; c += 4) {
        ulonglong2 th0a = *(const ulonglong2*)(thk + (c + 0) * OO + o8s2);
        ulonglong2 th0b = *(const ulonglong2*)(thk + (c + 0) * OO + o8s2 + 4);
        ulonglong2 th1a = *(const ulonglong2*)(thk + (c + 1) * OO + o8s2);
        ulonglong2 th1b = *(const ulonglong2*)(thk + (c + 1) * OO + o8s2 + 4);
        ulonglong2 th2a = *(const ulonglong2*)(thk + (c + 2) * OO + o8s2);
        ulonglong2 th2b = *(const ulonglong2*)(thk + (c + 2) * OO + o8s2 + 4);
        ulonglong2 th3a = *(const ulonglong2*)(thk + (c + 3) * OO + o8s2);
        ulonglong2 th3b = *(const ulonglong2*)(thk + (c + 3) * OO + o8s2 + 4);
        #pragma unroll
        for (int i = 0; i < R2; ++i) {
            ulonglong2 tm4 = *(const ulonglong2*)(Tm + mr[i] * TMP + c);
            float2 t01 = f2un(tm4.x);
            float2 t23 = f2un(tm4.y);
            ull d0 = f2dup(t01.x), d1 = f2dup(t01.y);
            ull d2 = f2dup(t23.x), d3 = f2dup(t23.y);
            a2[i][0] = f2fma(d0, th0a.x, a2[i][0]);
            a2[i][1] = f2fma(d0, th0a.y, a2[i][1]);
            a2[i][2] = f2fma(d0, th0b.x, a2[i][2]);
            a2[i][3] = f2fma(d0, th0b.y, a2[i][3]);
            a2[i][0] = f2fma(d1, th1a.x, a2[i][0]);
            a2[i][1] = f2fma(d1, th1a.y, a2[i][1]);
            a2[i][2] = f2fma(d1, th1b.x, a2[i][2]);
            a2[i][3] = f2fma(d1, th1b.y, a2[i][3]);
            a2[i][0] = f2fma(d2, th2a.x, a2[i][0]);
            a2[i][1] = f2fma(d2, th2a.y, a2[i][1]);
            a2[i][2] = f2fma(d2, th2b.x, a2[i][2]);
            a2[i][3] = f2fma(d2, th2b.y, a2[i][3]);
            a2[i][0] = f2fma(d3, th3a.x, a2[i][0]);
            a2[i][1] = f2fma(d3, th3a.y, a2[i][1]);
            a2[i][2] = f2fma(d3, th3b.x, a2[i][2]);
            a2[i][3] = f2fma(d3, th3b.y, a2[i][3]);
        }
    }
    #pragma unroll
    for (int i = 0; i < R2; ++i) {
        int m = m20 + i;
        if (m < CPAD) {              // pad rows hold finite junk x 0-cheb = ok
            ulonglong2* dst = (ulonglong2*)(Vv + (size_t)m * OO + o8s2);
            dst[0] = make_ulonglong2(a2[i][0], a2[i][1]);
            dst[1] = make_ulonglong2(a2[i][2], a2[i][3]);
        }
    }
}

// ---- stage 3: acc += chs[n][m] * V[m][o8..+8) over [mlo,mhi) ----
__device__ __forceinline__ void stage3_run(const float* __restrict__ chs,
                                           const float* __restrict__ Vv,
                                           ull (&acc)[R3][4],
                                           const int* __restrict__ croff,
                                           int o8, int mlo, int mhi, bool act3)
{
    if (!act3) return;
    #pragma unroll 1
    for (int m = mlo; m < mhi; m += 4) {
        float4 cb[R3];
        #pragma unroll
        for (int i = 0; i < R3; ++i)
            cb[i] = *(const float4*)(chs + croff[i] + m);
        const float* vp = Vv + (size_t)m * OO + o8;
        #pragma unroll
        for (int r = 0; r < 4; ++r) {
            ulonglong2 va = *(const ulonglong2*)(vp + r * OO);
            ulonglong2 vb = *(const ulonglong2*)(vp + r * OO + 4);
            #pragma unroll
            for (int i = 0; i < R3; ++i) {
                float cs = (r == 0) ? cb[i].x : (r == 1) ? cb[i].y
                         : (r == 2) ? cb[i].z : cb[i].w;
                ull d = f2dup(cs);
                acc[i][0] = f2fma(d, va.x, acc[i][0]);
                acc[i][1] = f2fma(d, va.y, acc[i][1]);
                acc[i][2] = f2fma(d, vb.x, acc[i][2]);
                acc[i][3] = f2fma(d, vb.y, acc[i][3]);
            }
        }
    }
}

__global__ void __launch_bounds__(NT, 1)
stgcn_fused_kernel(const float* __restrict__ x,
                   const float* __restrict__ theta,
                   const float* __restrict__ conv_w,
                   const float* __restrict__ conv_b,
                   const float* __restrict__ res_w,
                   const float* __restrict__ res_b,
                   float* __restrict__ out)
{
    extern __shared__ float sm[];
    float* wc   = sm + WC_OFF;
    float* wcb  = sm + WCB_OFF;
    float* wres = sm + WRES_OFF;
    float* wrb  = sm + WRB_OFF;
    float* xres = sm + XRES_OFF;
    float* xs   = sm + XS_OFF;
    float* chs  = sm + CHS_OFF;
    float* Tm   = sm + TM_OFF;
    float* Vv   = sm + V_OFF;
    float* ths  = sm + THS_OFF;
    const unsigned ths_u = s2u(ths);
    const unsigned chs_u = s2u(chs);

    const int t   = blockIdx.x;
    const int b   = blockIdx.y;
    const int tid = threadIdx.x;

    // G0: theta[0]
    for (int i = tid; i < THETA_CHUNKS; i += NT)
        CPA16(ths_u + i * 16, theta + (size_t)i * 4);
    CPCOMMIT();

    // ---------------- stage 0: xs + small weights ----------------
    for (int i = tid; i < FINq * 3 * NV; i += NT) {
        int f = i / (3 * NV);
        int r = i - f * (3 * NV);
        int s = r / NV;
        int m = r - s * NV;
        int tt = t + s - 1;
        float v = 0.0f;
        if (tt >= 0 && tt < TTq)
            v = x[((size_t)(b * FINq + f) * NV + m) * TTq + tt];
        xs[i] = v;                       // (f*3+s)*NV + m
    }
    for (int i = tid; i < HH * FINq * 3; i += NT) wc[i] = conv_w[i];
    if (tid < OO * FINq)              wres[tid]      = res_w[tid];
    else if (tid >= 192 && tid < 256) wcb[tid - 192] = conv_b[tid - 192];
    if (tid < OO)                     wrb[tid]       = res_b[tid];
    __syncthreads();

    // ---------------- stage 1: temporal conv + ReLU -> Tm[m][c] ----------------
    for (int idx = tid; idx < NV * HH; idx += NT) {
        int m = idx >> 6;
        int c = idx & 63;
        float v = wcb[c];
        #pragma unroll
        for (int f = 0; f < FINq; ++f)
            #pragma unroll
            for (int s = 0; s < 3; ++s)
                v = fmaf(xs[(f * 3 + s) * NV + m], wc[(c * FINq + f) * 3 + s], v);
        Tm[m * TMP + c] = fmaxf(v, 0.0f);
    }
    for (int i = tid; i < FINq * NV; i += NT) {
        int f = i / NV;
        int n = i - f * NV;
        xres[i] = xs[(f * 3 + 1) * NV + n];
    }
    __syncthreads();     // xs reads + Tm writes done

    // G1: cheb[1] slice (overwrites xs region)
    for (int i = tid; i < CHEB_CHUNKS; i += NT)
        CPA16(chs_u + i * 16, g_chebT + (size_t)i * 4);
    CPCOMMIT();
    CPWAIT(1);           // theta[0] landed
    __syncthreads();

    // ---- thread mappings ----
    const int o8s2 = (tid & 7) * 8;
    const int rg2  = tid >> 3;
    const int m20  = rg2 * R2;
    const bool act2 = (m20 < NV);

    const int half = tid >> 7;           // warps 0-3: half 0, warps 4-7: half 1
    const int htid = tid & 127;
    const int o8   = (htid & 7) * 8;
    const int rg3  = htid >> 3;
    const int n0   = rg3 * R3;
    const bool act3 = (rg3 < 15);
    const int mlo  = half ? 88 : 0;
    const int mhi  = half ? CPAD : 88;

    int croff[R3];
    #pragma unroll
    for (int i = 0; i < R3; ++i) {
        int n = n0 + i;
        croff[i] = ((n < NV) ? n : (NV - 1)) * CPAD;
    }

    ull acc[R3][4];
    #pragma unroll
    for (int i = 0; i < R3; ++i)
        #pragma unroll
        for (int p = 0; p < 4; ++p) acc[i][p] = 0ull;

    // ================= k = 0 : cheb[0] = I, acc := V0 =================
    stage2_run(ths, Tm, Vv, o8s2, m20, act2);     // V0 = Tm @ theta0
    __syncthreads();                              // V0 visible

    // G2: theta[1] (ths readers finished)
    {
        const float* tsrc = theta + (size_t)HH * OO;
        for (int i = tid; i < THETA_CHUNKS; i += NT)
            CPA16(ths_u + i * 16, tsrc + (size_t)i * 4);
        CPCOMMIT();
    }
    // acc init from V0 (half 0 only; half 1 contributes via the m-split sum)
    if (act3 && half == 0) {
        #pragma unroll
        for (int i = 0; i < R3; ++i) {
            int n = (n0 + i < NV) ? (n0 + i) : (NV - 1);
            const ulonglong2* src = (const ulonglong2*)(Vv + (size_t)n * OO + o8);
            ulonglong2 p0 = src[0], p1 = src[1];
            acc[i][0] = p0.x; acc[i][1] = p0.y;
            acc[i][2] = p1.x; acc[i][3] = p1.y;
        }
    }
    __syncthreads();     // V0 reads done; Vv free for k=1
    CPWAIT(0);           // cheb[1] + theta[1] landed
    __syncthreads();

    // ================= k = 1 =================
    stage2_run(ths, Tm, Vv, o8s2, m20, act2);     // V1
    __syncthreads();                              // V1 + nothing pending on ths
    {   // G3: theta[2]
        const float* tsrc = theta + (size_t)(2 * HH * OO);
        for (int i = tid; i < THETA_CHUNKS; i += NT)
            CPA16(ths_u + i * 16, tsrc + (size_t)i * 4);
        CPCOMMIT();
    }
    stage3_run(chs, Vv, acc, croff, o8, mlo, mhi, act3);   // += C1 @ V1
    __syncthreads();     // chs readers done
    {   // G4: cheb[2]
        const float* csrc = g_chebT + (size_t)NV * CPAD;
        for (int i = tid; i < CHEB_CHUNKS; i += NT)
            CPA16(chs_u + i * 16, csrc + (size_t)i * 4);
        CPCOMMIT();
    }
    CPWAIT(1);           // theta[2] ready (cheb[2] may pend)
    __syncthreads();

    // ================= k = 2 =================
    stage2_run(ths, Tm, Vv, o8s2, m20, act2);     // V2 (stage3 k=1 done)
    __syncthreads();
    CPWAIT(0);           // cheb[2] landed
    __syncthreads();
    stage3_run(chs, Vv, acc, croff, o8, mlo, mhi, act3);   // += C2 @ V2

    // ---------------- cross-half reduce via chs region (now free) ----------------
    __syncthreads();
    if (act3 && half == 1) {
        #pragma unroll
        for (int i = 0; i < R3; ++i) {
            ulonglong2* dst = (ulonglong2*)(chs + (size_t)(n0 + i) * OO + o8);
            dst[0] = make_ulonglong2(acc[i][0], acc[i][1]);
            dst[1] = make_ulonglong2(acc[i][2], acc[i][3]);
        }
    }
    __syncthreads();

    // ---------------- epilogue (half 0): add partner, relu + residual ----------------
    if (act3 && half == 0) {
        #pragma unroll
        for (int i = 0; i < R3; ++i) {
            int n = n0 + i;
            if (n >= NV) break;
            const ulonglong2* src = (const ulonglong2*)(chs + (size_t)n * OO + o8);
            ulonglong2 p0 = src[0], p1 = src[1];
            acc[i][0] = f2add(acc[i][0], p0.x);
            acc[i][1] = f2add(acc[i][1], p0.y);
            acc[i][2] = f2add(acc[i][2], p1.x);
            acc[i][3] = f2add(acc[i][3], p1.y);
            float x0 = xres[n];
            float x1 = xres[NV + n];
            float x2 = xres[2 * NV + n];
            #pragma unroll
            for (int p = 0; p < 4; ++p) {
                float2 gv = f2un(acc[i][p]);
                int o0 = o8 + 2 * p;
                float r0 = wrb[o0] + x0 * wres[o0 * 3 + 0]
                                   + x1 * wres[o0 * 3 + 1]
                                   + x2 * wres[o0 * 3 + 2];
                float r1 = wrb[o0 + 1] + x0 * wres[(o0 + 1) * 3 + 0]
                                       + x1 * wres[(o0 + 1) * 3 + 1]
                                       + x2 * wres[(o0 + 1) * 3 + 2];
                out[((size_t)(b * OO + o0)     * NV + n) * TTq + t] = fmaxf(gv.x, 0.0f) + r0;
                out[((size_t)(b * OO + o0 + 1) * NV + n) * TTq + t] = fmaxf(gv.y, 0.0f) + r1;
            }
        }
    }
}

extern "C" void kernel_launch(void* const* d_in, const int* in_sizes, int n_in,
                              void* d_out, int out_size)
{
    (void)in_sizes; (void)n_in; (void)out_size;
    const float* x      = (const float*)d_in[0];
    // d_in[1] = adj (unused by forward)
    const float* cheb   = (const float*)d_in[2];
    const float* conv_w = (const float*)d_in[3];
    const float* conv_b = (const float*)d_in[4];
    const float* theta  = (const float*)d_in[5];
    const float* res_w  = (const float*)d_in[6];
    const float* res_b  = (const float*)d_in[7];
    float* out = (float*)d_out;

    prep_chebT<<<(2 * NV * CPAD + 255) / 256, 256>>>(cheb);

    cudaFuncSetAttribute(stgcn_fused_kernel,
                         cudaFuncAttributeMaxDynamicSharedMemorySize, SMEM_BYTES);

    dim3 grid(TTq, 16);   // 4608 CTAs, one per (b, t)
    stgcn_fused_kernel<<<grid, NT, SMEM_BYTES>>>(
        x, theta, conv_w, conv_b, res_w, res_b, out);
}